// round 1
// baseline (speedup 1.0000x reference)
#include <cuda_runtime.h>
#include <cuda_bf16.h>

// Problem constants (fixed by the dataset)
#define EMB   128      // embedding dim (32 float4 per vector)
#define CWIN  20       // context window
#define NNEG  20       // negatives
#define WARPS_PER_BLOCK 8
#define THREADS (WARPS_PER_BLOCK * 32)

// scratch for deterministic two-stage reduction (max blocks = 16384/8 = 2048)
__device__ float g_partials[4096];

__device__ __forceinline__ float softplus_clip(float x) {
    // clip to [-10,10] then log(1+exp(x))
    x = fminf(fmaxf(x, -10.0f), 10.0f);
    return log1pf(__expf(x));
}

__global__ __launch_bounds__(THREADS)
void cbow_row_kernel(const int*   __restrict__ pos_target,
                     const int*   __restrict__ pos_contexts,
                     const int*   __restrict__ pos_negatives,
                     const float* __restrict__ context_table,
                     const float* __restrict__ output_table,
                     int B)
{
    const int warp = (blockIdx.x * blockDim.x + threadIdx.x) >> 5;
    const int lane = threadIdx.x & 31;

    float loss = 0.0f;

    if (warp < B) {
        const int row = warp;
        const float4* __restrict__ ctab = (const float4*)context_table;
        const float4* __restrict__ otab = (const float4*)output_table;

        // ---- sum of context embeddings (each lane holds 4 of 128 dims) ----
        float4 acc = make_float4(0.f, 0.f, 0.f, 0.f);
        #pragma unroll
        for (int c = 0; c < CWIN; ++c) {
            int idx = __ldg(&pos_contexts[row * CWIN + c]);
            float4 v = __ldg(&ctab[(long)idx * (EMB / 4) + lane]);
            acc.x += v.x; acc.y += v.y; acc.z += v.z; acc.w += v.w;
        }

        // ---- target partial dot ----
        int ti = __ldg(&pos_target[row]);
        float4 t = __ldg(&otab[(long)ti * (EMB / 4) + lane]);
        float pd = acc.x * t.x + acc.y * t.y + acc.z * t.z + acc.w * t.w;

        // ---- negative partial dots (independent loads -> high MLP) ----
        float nd[NNEG];
        #pragma unroll
        for (int n = 0; n < NNEG; ++n) {
            int idx = __ldg(&pos_negatives[row * NNEG + n]);
            float4 v = __ldg(&otab[(long)idx * (EMB / 4) + lane]);
            nd[n] = acc.x * v.x + acc.y * v.y + acc.z * v.z + acc.w * v.w;
        }

        // ---- one interleaved butterfly reduction for all 21 partials ----
        #pragma unroll
        for (int off = 16; off > 0; off >>= 1) {
            pd += __shfl_xor_sync(0xFFFFFFFFu, pd, off);
            #pragma unroll
            for (int n = 0; n < NNEG; ++n)
                nd[n] += __shfl_xor_sync(0xFFFFFFFFu, nd[n], off);
        }

        // ---- loss:  softplus(-pos) + sum softplus(neg) ----
        loss = softplus_clip(-pd);
        // note: clip(-x) == -clip(x), so softplus_clip(-pd) == log1p(exp(-clip(pd)))
        #pragma unroll
        for (int n = 0; n < NNEG; ++n)
            loss += softplus_clip(nd[n]);
    }

    // ---- block reduction (deterministic) ----
    __shared__ float smem[WARPS_PER_BLOCK];
    if (lane == 0) smem[threadIdx.x >> 5] = loss;
    __syncthreads();
    if (threadIdx.x == 0) {
        float s = 0.0f;
        #pragma unroll
        for (int w = 0; w < WARPS_PER_BLOCK; ++w) s += smem[w];
        g_partials[blockIdx.x] = s;
    }
}

__global__ void cbow_reduce_kernel(float* __restrict__ out, int nparts, float invB)
{
    __shared__ float smem[1024];
    float s = 0.0f;
    for (int i = threadIdx.x; i < nparts; i += blockDim.x)
        s += g_partials[i];
    smem[threadIdx.x] = s;
    __syncthreads();
    for (int step = blockDim.x >> 1; step > 0; step >>= 1) {
        if (threadIdx.x < step) smem[threadIdx.x] += smem[threadIdx.x + step];
        __syncthreads();
    }
    if (threadIdx.x == 0) out[0] = smem[0] * invB;
}

extern "C" void kernel_launch(void* const* d_in, const int* in_sizes, int n_in,
                              void* d_out, int out_size)
{
    const int*   pos_target    = (const int*)  d_in[0];
    const int*   pos_contexts  = (const int*)  d_in[1];
    const int*   pos_negatives = (const int*)  d_in[2];
    const float* context_table = (const float*)d_in[3];
    const float* output_table  = (const float*)d_in[4];
    float* out = (float*)d_out;

    const int B = in_sizes[0];                       // 16384
    const int nblocks = (B + WARPS_PER_BLOCK - 1) / WARPS_PER_BLOCK;

    cbow_row_kernel<<<nblocks, THREADS>>>(pos_target, pos_contexts, pos_negatives,
                                          context_table, output_table, B);
    cbow_reduce_kernel<<<1, 1024>>>(out, nblocks, 1.0f / (float)B);
}

// round 2
// speedup vs baseline: 1.1635x; 1.1635x over previous
#include <cuda_runtime.h>
#include <cuda_bf16.h>

// Problem constants (fixed by the dataset)
#define EMB   128      // embedding dim (32 float4 per vector)
#define CWIN  20       // context window
#define NNEG  20       // negatives
#define WARPS_PER_BLOCK 8
#define THREADS (WARPS_PER_BLOCK * 32)

// scratch for deterministic single-pass reduction (blocks = 16384/8 = 2048)
__device__ float        g_partials[4096];
__device__ unsigned int g_counter = 0;

__device__ __forceinline__ float softplus_clip(float x) {
    // clip to [-10,10] then log(1+exp(x)); fast intrinsics are safe here:
    // terms are O(0.7) and tolerance is 1e-3 on the mean.
    x = fminf(fmaxf(x, -10.0f), 10.0f);
    return __logf(1.0f + __expf(x));
}

__global__ __launch_bounds__(THREADS)
void cbow_fused_kernel(const int*   __restrict__ pos_target,
                       const int*   __restrict__ pos_contexts,
                       const int*   __restrict__ pos_negatives,
                       const float* __restrict__ context_table,
                       const float* __restrict__ output_table,
                       float*       __restrict__ out,
                       int B, float invB)
{
    const int warp = (blockIdx.x * blockDim.x + threadIdx.x) >> 5;
    const int lane = threadIdx.x & 31;

    float loss = 0.0f;

    if (warp < B) {
        const int row = warp;
        const float4* __restrict__ ctab = (const float4*)context_table;
        const float4* __restrict__ otab = (const float4*)output_table;

        // ---- sum of context embeddings (each lane holds 4 of 128 dims) ----
        float4 acc = make_float4(0.f, 0.f, 0.f, 0.f);
        #pragma unroll
        for (int c = 0; c < CWIN; ++c) {
            int idx = __ldg(&pos_contexts[row * CWIN + c]);
            float4 v = __ldg(&ctab[(long)idx * (EMB / 4) + lane]);
            acc.x += v.x; acc.y += v.y; acc.z += v.z; acc.w += v.w;
        }

        // ---- target partial dot ----
        int ti = __ldg(&pos_target[row]);
        float4 t = __ldg(&otab[(long)ti * (EMB / 4) + lane]);
        float pd = acc.x * t.x + acc.y * t.y + acc.z * t.z + acc.w * t.w;

        // ---- negative partial dots (independent loads -> high MLP) ----
        float nd[NNEG];
        #pragma unroll
        for (int n = 0; n < NNEG; ++n) {
            int idx = __ldg(&pos_negatives[row * NNEG + n]);
            float4 v = __ldg(&otab[(long)idx * (EMB / 4) + lane]);
            nd[n] = acc.x * v.x + acc.y * v.y + acc.z * v.z + acc.w * v.w;
        }

        // ---- one interleaved butterfly reduction for all 21 partials ----
        #pragma unroll
        for (int off = 16; off > 0; off >>= 1) {
            pd += __shfl_xor_sync(0xFFFFFFFFu, pd, off);
            #pragma unroll
            for (int n = 0; n < NNEG; ++n)
                nd[n] += __shfl_xor_sync(0xFFFFFFFFu, nd[n], off);
        }

        // ---- loss: softplus(-pos) + sum softplus(neg) ----
        loss = softplus_clip(-pd);
        #pragma unroll
        for (int n = 0; n < NNEG; ++n)
            loss += softplus_clip(nd[n]);
    }

    // ---- per-block reduction (deterministic order) ----
    __shared__ float smem[WARPS_PER_BLOCK];
    __shared__ bool  s_is_last;
    if (lane == 0) smem[threadIdx.x >> 5] = loss;
    __syncthreads();
    if (threadIdx.x == 0) {
        float s = 0.0f;
        #pragma unroll
        for (int w = 0; w < WARPS_PER_BLOCK; ++w) s += smem[w];
        g_partials[blockIdx.x] = s;
        __threadfence();   // publish partial before signaling
        unsigned int t = atomicAdd(&g_counter, 1u);
        s_is_last = (t == gridDim.x - 1);
    }
    __syncthreads();

    // ---- last block to arrive does the final deterministic reduction ----
    if (s_is_last) {
        const int nparts = gridDim.x;
        float s = 0.0f;
        for (int i = threadIdx.x; i < nparts; i += THREADS)
            s += g_partials[i];                 // fixed index order -> deterministic

        __shared__ float rsm[THREADS];
        rsm[threadIdx.x] = s;
        __syncthreads();
        #pragma unroll
        for (int step = THREADS >> 1; step > 0; step >>= 1) {
            if (threadIdx.x < step) rsm[threadIdx.x] += rsm[threadIdx.x + step];
            __syncthreads();
        }
        if (threadIdx.x == 0) {
            out[0] = rsm[0] * invB;
            g_counter = 0;                      // reset for next (graph) replay
        }
    }
}

extern "C" void kernel_launch(void* const* d_in, const int* in_sizes, int n_in,
                              void* d_out, int out_size)
{
    const int*   pos_target    = (const int*)  d_in[0];
    const int*   pos_contexts  = (const int*)  d_in[1];
    const int*   pos_negatives = (const int*)  d_in[2];
    const float* context_table = (const float*)d_in[3];
    const float* output_table  = (const float*)d_in[4];
    float* out = (float*)d_out;

    const int B = in_sizes[0];                       // 16384
    const int nblocks = (B + WARPS_PER_BLOCK - 1) / WARPS_PER_BLOCK;

    cbow_fused_kernel<<<nblocks, THREADS>>>(pos_target, pos_contexts, pos_negatives,
                                            context_table, output_table, out,
                                            B, 1.0f / (float)B);
}

// round 3
// speedup vs baseline: 1.2968x; 1.1145x over previous
#include <cuda_runtime.h>
#include <cuda_bf16.h>

// Problem constants (fixed by the dataset)
#define EMB   128      // embedding dim (32 float4 per vector)
#define CWIN  20       // context window
#define NNEG  20       // negatives
#define NCHUNK 5       // negatives processed per register chunk
#define WARPS_PER_BLOCK 8
#define THREADS (WARPS_PER_BLOCK * 32)

// scratch for deterministic single-pass reduction (blocks = 16384/8 = 2048)
__device__ float        g_partials[4096];
__device__ unsigned int g_counter = 0;

__device__ __forceinline__ float softplus_clip(float x) {
    // clip to [-10,10] then log(1+exp(x)); fast intrinsics are safe:
    // terms are O(0.7) and tolerance is 1e-3 on the mean.
    x = fminf(fmaxf(x, -10.0f), 10.0f);
    return __logf(1.0f + __expf(x));
}

__global__ __launch_bounds__(THREADS, 6)
void cbow_fused_kernel(const int*   __restrict__ pos_target,
                       const int*   __restrict__ pos_contexts,
                       const int*   __restrict__ pos_negatives,
                       const float* __restrict__ context_table,
                       const float* __restrict__ output_table,
                       float*       __restrict__ out,
                       int B, float invB)
{
    const int warp = (blockIdx.x * blockDim.x + threadIdx.x) >> 5;
    const int lane = threadIdx.x & 31;

    float loss = 0.0f;

    if (warp < B) {
        const int row = warp;
        const float4* __restrict__ ctab = (const float4*)context_table;
        const float4* __restrict__ otab = (const float4*)output_table;

        // ---- coalesced index prefetch: 2 lane-parallel LDGs + broadcast ----
        int ctx_idx = 0, neg_idx = 0;
        if (lane < CWIN) ctx_idx = __ldg(&pos_contexts[row * CWIN + lane]);
        if (lane < NNEG) neg_idx = __ldg(&pos_negatives[row * NNEG + lane]);
        const int tgt = __ldg(&pos_target[row]);

        // ---- sum of context embeddings (each lane holds 4 of 128 dims) ----
        float4 acc = make_float4(0.f, 0.f, 0.f, 0.f);
        #pragma unroll
        for (int c = 0; c < CWIN; ++c) {
            unsigned idx = (unsigned)__shfl_sync(0xFFFFFFFFu, ctx_idx, c);
            float4 v = __ldg(&ctab[idx * (EMB / 4u) + lane]);
            acc.x += v.x; acc.y += v.y; acc.z += v.z; acc.w += v.w;
        }

        // ---- target dot ----
        float4 t = __ldg(&otab[(unsigned)tgt * (EMB / 4u) + lane]);
        float pd = acc.x * t.x + acc.y * t.y + acc.z * t.z + acc.w * t.w;
        #pragma unroll
        for (int off = 16; off > 0; off >>= 1)
            pd += __shfl_xor_sync(0xFFFFFFFFu, pd, off);
        loss = softplus_clip(-pd);

        // ---- negatives in chunks of NCHUNK: keeps register pressure low,
        //      each chunk exposes NCHUNK independent gathers ----
        #pragma unroll
        for (int base = 0; base < NNEG; base += NCHUNK) {
            float nd[NCHUNK];
            #pragma unroll
            for (int n = 0; n < NCHUNK; ++n) {
                unsigned idx = (unsigned)__shfl_sync(0xFFFFFFFFu, neg_idx, base + n);
                float4 v = __ldg(&otab[idx * (EMB / 4u) + lane]);
                nd[n] = acc.x * v.x + acc.y * v.y + acc.z * v.z + acc.w * v.w;
            }
            #pragma unroll
            for (int off = 16; off > 0; off >>= 1) {
                #pragma unroll
                for (int n = 0; n < NCHUNK; ++n)
                    nd[n] += __shfl_xor_sync(0xFFFFFFFFu, nd[n], off);
            }
            #pragma unroll
            for (int n = 0; n < NCHUNK; ++n)
                loss += softplus_clip(nd[n]);
        }
    }

    // ---- per-block reduction (deterministic order) ----
    __shared__ float smem[WARPS_PER_BLOCK];
    __shared__ bool  s_is_last;
    if (lane == 0) smem[threadIdx.x >> 5] = loss;
    __syncthreads();
    if (threadIdx.x == 0) {
        float s = 0.0f;
        #pragma unroll
        for (int w = 0; w < WARPS_PER_BLOCK; ++w) s += smem[w];
        g_partials[blockIdx.x] = s;
        __threadfence();   // publish partial before signaling
        unsigned int t = atomicAdd(&g_counter, 1u);
        s_is_last = (t == gridDim.x - 1);
    }
    __syncthreads();

    // ---- last block to arrive does the final deterministic reduction ----
    if (s_is_last) {
        const int nparts = gridDim.x;
        float s = 0.0f;
        for (int i = threadIdx.x; i < nparts; i += THREADS)
            s += g_partials[i];                 // fixed index order -> deterministic

        __shared__ float rsm[THREADS];
        rsm[threadIdx.x] = s;
        __syncthreads();
        #pragma unroll
        for (int step = THREADS >> 1; step > 0; step >>= 1) {
            if (threadIdx.x < step) rsm[threadIdx.x] += rsm[threadIdx.x + step];
            __syncthreads();
        }
        if (threadIdx.x == 0) {
            out[0] = rsm[0] * invB;
            g_counter = 0;                      // reset for next (graph) replay
        }
    }
}

extern "C" void kernel_launch(void* const* d_in, const int* in_sizes, int n_in,
                              void* d_out, int out_size)
{
    const int*   pos_target    = (const int*)  d_in[0];
    const int*   pos_contexts  = (const int*)  d_in[1];
    const int*   pos_negatives = (const int*)  d_in[2];
    const float* context_table = (const float*)d_in[3];
    const float* output_table  = (const float*)d_in[4];
    float* out = (float*)d_out;

    const int B = in_sizes[0];                       // 16384
    const int nblocks = (B + WARPS_PER_BLOCK - 1) / WARPS_PER_BLOCK;

    cbow_fused_kernel<<<nblocks, THREADS>>>(pos_target, pos_contexts, pos_negatives,
                                            context_table, output_table, out,
                                            B, 1.0f / (float)B);
}

// round 4
// speedup vs baseline: 1.3067x; 1.0077x over previous
#include <cuda_runtime.h>
#include <cuda_bf16.h>
#include <string.h>

// Problem constants (fixed by the dataset)
#define EMB    128      // embedding dim (32 float4 per vector)
#define CWIN   20       // context window
#define NNEG   20       // negatives
#define NCH    4        // negatives per pipelined chunk (5 chunks)
#define WARPS_PER_BLOCK 8
#define THREADS (WARPS_PER_BLOCK * 32)
#define NBLK   912      // persistent grid: 152 SMs * 6 blocks

// scratch for deterministic single-pass reduction
__device__ float        g_partials[4096];
__device__ unsigned int g_counter = 0;

typedef unsigned long long ull;

__device__ __forceinline__ ull pk2(float a, float b) {
    ull r; asm("mov.b64 %0, {%1, %2};" : "=l"(r) : "f"(a), "f"(b)); return r;
}
__device__ __forceinline__ float upk_sum(ull v) {
    float a, b; asm("mov.b64 {%0, %1}, %2;" : "=f"(a), "=f"(b) : "l"(v));
    return a + b;
}
__device__ __forceinline__ ull add2(ull a, ull b) {
    ull r; asm("add.rn.f32x2 %0, %1, %2;" : "=l"(r) : "l"(a), "l"(b)); return r;
}
__device__ __forceinline__ ull mul2(ull a, ull b) {
    ull r; asm("mul.rn.f32x2 %0, %1, %2;" : "=l"(r) : "l"(a), "l"(b)); return r;
}
__device__ __forceinline__ ull fma2(ull a, ull b, ull c) {
    ull r; asm("fma.rn.f32x2 %0, %1, %2, %3;" : "=l"(r) : "l"(a), "l"(b), "l"(c)); return r;
}

__device__ __forceinline__ float clip10(float x) {
    return fminf(fmaxf(x, -10.0f), 10.0f);
}

__global__ __launch_bounds__(THREADS, 6)
void cbow_fused_kernel(const int*   __restrict__ pos_target,
                       const int*   __restrict__ pos_contexts,
                       const int*   __restrict__ pos_negatives,
                       const float* __restrict__ context_table,
                       const float* __restrict__ output_table,
                       float*       __restrict__ out,
                       int B, float invB)
{
    const int lane = threadIdx.x & 31;
    const unsigned warp_gid = (blockIdx.x * blockDim.x + threadIdx.x) >> 5;
    const unsigned total_warps = gridDim.x * WARPS_PER_BLOCK;

    const float4* __restrict__ ctab = (const float4*)context_table;
    const float4* __restrict__ otab = (const float4*)output_table;

    float loss = 0.0f;

    for (unsigned row = warp_gid; row < (unsigned)B; row += total_warps) {
        // ---- coalesced index prefetch (2 lane-parallel LDGs + broadcast) ----
        int ctx_i = 0, neg_i = 0;
        if (lane < CWIN) ctx_i = __ldg(&pos_contexts[row * CWIN + lane]);
        if (lane < NNEG) neg_i = __ldg(&pos_negatives[row * NNEG + lane]);
        const int tgt = __ldg(&pos_target[row]);

        // issue target gather early — overlaps with context accumulation
        float4 tv = __ldg(&otab[(unsigned)tgt * (EMB / 4u) + lane]);

        // ---- context sum: packed f32x2 accumulation ----
        ull a01 = 0ull, a23 = 0ull;   // bits of (0.f, 0.f)
        #pragma unroll
        for (int c = 0; c < CWIN; ++c) {
            unsigned idx = (unsigned)__shfl_sync(0xFFFFFFFFu, ctx_i, c);
            float4 v = __ldg(&ctab[idx * (EMB / 4u) + lane]);
            a01 = add2(a01, pk2(v.x, v.y));
            a23 = add2(a23, pk2(v.z, v.w));
        }

        // ---- prefetch negative chunk 0 (overlaps target dot below) ----
        float4 pv[NCH];
        #pragma unroll
        for (int j = 0; j < NCH; ++j) {
            unsigned idx = (unsigned)__shfl_sync(0xFFFFFFFFu, neg_i, j);
            pv[j] = __ldg(&otab[idx * (EMB / 4u) + lane]);
        }

        // ---- target dot + reduce + positive loss ----
        float pd = upk_sum(fma2(a01, pk2(tv.x, tv.y),
                                mul2(a23, pk2(tv.z, tv.w))));
        #pragma unroll
        for (int off = 16; off > 0; off >>= 1)
            pd += __shfl_xor_sync(0xFFFFFFFFu, pd, off);
        loss += __logf(1.0f + __expf(-clip10(pd)));   // softplus(-clip(pd))

        // ---- negatives: pipelined chunks of NCH ----
        #pragma unroll
        for (int base = 0; base < NNEG; base += NCH) {
            // consume prefetched vectors into partial dots
            float nd[NCH];
            #pragma unroll
            for (int j = 0; j < NCH; ++j) {
                nd[j] = upk_sum(fma2(a01, pk2(pv[j].x, pv[j].y),
                                     mul2(a23, pk2(pv[j].z, pv[j].w))));
            }
            // issue next chunk's gathers NOW; butterfly below hides latency
            if (base + NCH < NNEG) {
                #pragma unroll
                for (int j = 0; j < NCH; ++j) {
                    unsigned idx = (unsigned)__shfl_sync(0xFFFFFFFFu, neg_i, base + NCH + j);
                    pv[j] = __ldg(&otab[idx * (EMB / 4u) + lane]);
                }
            }
            // interleaved butterfly for NCH independent reductions
            #pragma unroll
            for (int off = 16; off > 0; off >>= 1) {
                #pragma unroll
                for (int j = 0; j < NCH; ++j)
                    nd[j] += __shfl_xor_sync(0xFFFFFFFFu, nd[j], off);
            }
            // sum of softplus via single log of product:
            // max product = (1+e^10)^4 ~ 2.4e17 << f32 max
            float prod = 1.0f;
            #pragma unroll
            for (int j = 0; j < NCH; ++j)
                prod *= (1.0f + __expf(clip10(nd[j])));
            loss += __logf(prod);
        }
    }

    // ---- per-block reduction (deterministic order) ----
    __shared__ float smem[WARPS_PER_BLOCK];
    __shared__ bool  s_is_last;
    if (lane == 0) smem[threadIdx.x >> 5] = loss;
    __syncthreads();
    if (threadIdx.x == 0) {
        float s = 0.0f;
        #pragma unroll
        for (int w = 0; w < WARPS_PER_BLOCK; ++w) s += smem[w];
        g_partials[blockIdx.x] = s;
        __threadfence();   // publish partial before signaling
        unsigned int t = atomicAdd(&g_counter, 1u);
        s_is_last = (t == gridDim.x - 1);
    }
    __syncthreads();

    // ---- last block performs the final deterministic reduction ----
    if (s_is_last) {
        const int nparts = gridDim.x;
        float s = 0.0f;
        for (int i = threadIdx.x; i < nparts; i += THREADS)
            s += g_partials[i];                 // fixed index order -> deterministic

        __shared__ float rsm[THREADS];
        rsm[threadIdx.x] = s;
        __syncthreads();
        #pragma unroll
        for (int step = THREADS >> 1; step > 0; step >>= 1) {
            if (threadIdx.x < step) rsm[threadIdx.x] += rsm[threadIdx.x + step];
            __syncthreads();
        }
        if (threadIdx.x == 0) {
            out[0] = rsm[0] * invB;
            g_counter = 0;                      // reset for next (graph) replay
        }
    }
}

extern "C" void kernel_launch(void* const* d_in, const int* in_sizes, int n_in,
                              void* d_out, int out_size)
{
    const int*   pos_target    = (const int*)  d_in[0];
    const int*   pos_contexts  = (const int*)  d_in[1];
    const int*   pos_negatives = (const int*)  d_in[2];
    const float* context_table = (const float*)d_in[3];
    const float* output_table  = (const float*)d_in[4];
    float* out = (float*)d_out;

    const int B = in_sizes[0];                       // 16384

    cbow_fused_kernel<<<NBLK, THREADS>>>(pos_target, pos_contexts, pos_negatives,
                                         context_table, output_table, out,
                                         B, 1.0f / (float)B);
}

// round 5
// speedup vs baseline: 1.3811x; 1.0569x over previous
#include <cuda_runtime.h>
#include <cuda_bf16.h>

// Problem constants (fixed by the dataset)
#define EMB    128      // embedding dim (32 float4 per vector)
#define CWIN   20       // context window
#define NNEG   20       // negatives
#define NCH    4        // negatives per chunk (5 chunks)
#define WARPS_PER_BLOCK 8
#define THREADS (WARPS_PER_BLOCK * 32)
#define NBLK   1216     // persistent grid: 152 SMs * 8 blocks

// scratch for deterministic single-pass reduction
__device__ float        g_partials[4096];
__device__ unsigned int g_counter = 0;

typedef unsigned long long ull;

__device__ __forceinline__ ull pk2(float a, float b) {
    ull r; asm("mov.b64 %0, {%1, %2};" : "=l"(r) : "f"(a), "f"(b)); return r;
}
__device__ __forceinline__ float upk_sum(ull v) {
    float a, b; asm("mov.b64 {%0, %1}, %2;" : "=f"(a), "=f"(b) : "l"(v));
    return a + b;
}
__device__ __forceinline__ ull add2(ull a, ull b) {
    ull r; asm("add.rn.f32x2 %0, %1, %2;" : "=l"(r) : "l"(a), "l"(b)); return r;
}
__device__ __forceinline__ ull mul2(ull a, ull b) {
    ull r; asm("mul.rn.f32x2 %0, %1, %2;" : "=l"(r) : "l"(a), "l"(b)); return r;
}
__device__ __forceinline__ ull fma2(ull a, ull b, ull c) {
    ull r; asm("fma.rn.f32x2 %0, %1, %2, %3;" : "=l"(r) : "l"(a), "l"(b), "l"(c)); return r;
}

__device__ __forceinline__ float clip10(float x) {
    return fminf(fmaxf(x, -10.0f), 10.0f);
}

__global__ __launch_bounds__(THREADS, 8)   // force <=32 regs -> 64 warps/SM
void cbow_fused_kernel(const int*   __restrict__ pos_target,
                       const int*   __restrict__ pos_contexts,
                       const int*   __restrict__ pos_negatives,
                       const float* __restrict__ context_table,
                       const float* __restrict__ output_table,
                       float*       __restrict__ out,
                       int B, float invB)
{
    const int lane = threadIdx.x & 31;
    const unsigned warp_gid = (blockIdx.x * blockDim.x + threadIdx.x) >> 5;
    const unsigned total_warps = gridDim.x * WARPS_PER_BLOCK;

    const float4* __restrict__ ctab = (const float4*)context_table;
    const float4* __restrict__ otab = (const float4*)output_table;

    float loss = 0.0f;

    for (unsigned row = warp_gid; row < (unsigned)B; row += total_warps) {
        // ---- coalesced index prefetch (2 lane-parallel LDGs + broadcast) ----
        int ctx_i = 0, neg_i = 0;
        if (lane < CWIN) ctx_i = __ldg(&pos_contexts[row * CWIN + lane]);
        if (lane < NNEG) neg_i = __ldg(&pos_negatives[row * NNEG + lane]);
        const int tgt = __ldg(&pos_target[row]);

        // ---- context sum: packed f32x2 accumulation ----
        ull a01 = 0ull, a23 = 0ull;
        #pragma unroll
        for (int c = 0; c < CWIN; ++c) {
            unsigned idx = (unsigned)__shfl_sync(0xFFFFFFFFu, ctx_i, c);
            float4 v = __ldg(&ctab[idx * (EMB / 4u) + lane]);
            a01 = add2(a01, pk2(v.x, v.y));
            a23 = add2(a23, pk2(v.z, v.w));
        }

        // ---- target dot + reduce + positive loss ----
        {
            float4 tv = __ldg(&otab[(unsigned)tgt * (EMB / 4u) + lane]);
            float pd = upk_sum(fma2(a01, pk2(tv.x, tv.y),
                                    mul2(a23, pk2(tv.z, tv.w))));
            #pragma unroll
            for (int off = 16; off > 0; off >>= 1)
                pd += __shfl_xor_sync(0xFFFFFFFFu, pd, off);
            loss += __logf(1.0f + __expf(-clip10(pd)));
        }

        // ---- negatives: chunks of NCH (compiler batches the NCH gathers) ----
        #pragma unroll
        for (int base = 0; base < NNEG; base += NCH) {
            float nd[NCH];
            #pragma unroll
            for (int j = 0; j < NCH; ++j) {
                unsigned idx = (unsigned)__shfl_sync(0xFFFFFFFFu, neg_i, base + j);
                float4 v = __ldg(&otab[idx * (EMB / 4u) + lane]);
                nd[j] = upk_sum(fma2(a01, pk2(v.x, v.y),
                                     mul2(a23, pk2(v.z, v.w))));
            }
            #pragma unroll
            for (int off = 16; off > 0; off >>= 1) {
                #pragma unroll
                for (int j = 0; j < NCH; ++j)
                    nd[j] += __shfl_xor_sync(0xFFFFFFFFu, nd[j], off);
            }
            // sum of softplus via single log of a product:
            // max product = (1+e^10)^4 ~ 2.4e17 << f32 max
            float prod = 1.0f;
            #pragma unroll
            for (int j = 0; j < NCH; ++j)
                prod *= (1.0f + __expf(clip10(nd[j])));
            loss += __logf(prod);
        }
    }

    // ---- per-block reduction (deterministic order) ----
    __shared__ float smem[WARPS_PER_BLOCK];
    __shared__ bool  s_is_last;
    if (lane == 0) smem[threadIdx.x >> 5] = loss;
    __syncthreads();
    if (threadIdx.x == 0) {
        float s = 0.0f;
        #pragma unroll
        for (int w = 0; w < WARPS_PER_BLOCK; ++w) s += smem[w];
        g_partials[blockIdx.x] = s;
        __threadfence();   // publish partial before signaling
        unsigned int t = atomicAdd(&g_counter, 1u);
        s_is_last = (t == gridDim.x - 1);
    }
    __syncthreads();

    // ---- last block performs the final deterministic reduction ----
    if (s_is_last) {
        const int nparts = gridDim.x;
        float s = 0.0f;
        for (int i = threadIdx.x; i < nparts; i += THREADS)
            s += g_partials[i];                 // fixed index order -> deterministic

        __shared__ float rsm[THREADS];
        rsm[threadIdx.x] = s;
        __syncthreads();
        #pragma unroll
        for (int step = THREADS >> 1; step > 0; step >>= 1) {
            if (threadIdx.x < step) rsm[threadIdx.x] += rsm[threadIdx.x + step];
            __syncthreads();
        }
        if (threadIdx.x == 0) {
            out[0] = rsm[0] * invB;
            g_counter = 0;                      // reset for next (graph) replay
        }
    }
}

extern "C" void kernel_launch(void* const* d_in, const int* in_sizes, int n_in,
                              void* d_out, int out_size)
{
    const int*   pos_target    = (const int*)  d_in[0];
    const int*   pos_contexts  = (const int*)  d_in[1];
    const int*   pos_negatives = (const int*)  d_in[2];
    const float* context_table = (const float*)d_in[3];
    const float* output_table  = (const float*)d_in[4];
    float* out = (float*)d_out;

    const int B = in_sizes[0];                       // 16384

    cbow_fused_kernel<<<NBLK, THREADS>>>(pos_target, pos_contexts, pos_negatives,
                                         context_table, output_table, out,
                                         B, 1.0f / (float)B);
}